// round 1
// baseline (speedup 1.0000x reference)
#include <cuda_runtime.h>
#include <cstdint>

// Problem constants (fixed by the dataset)
#define BB 128
#define AA 8732
#define NN (BB * AA)        // 1,117,696  ( = 256 * 4366, divisible by 4 )
#define CC 21
#define NBUCKET 65536
#define BACKGROUND 0

// ---------------------------------------------------------------------------
// Device scratch (no allocations allowed)
// ---------------------------------------------------------------------------
__device__ unsigned int g_ce_bits[NN];
__device__ unsigned int g_hist1[NBUCKET];
__device__ unsigned int g_hist2[NBUCKET];

struct State {
    unsigned long long num_pos;
    double             pos_ce_sum;
    double             loc_sum;
    unsigned long long k;           // min(3*num_pos, num_neg)
    unsigned long long k_rem;       // how many needed from the selected top-16 bucket
    unsigned long long cnt_above1;  // count with top16 bits strictly above prefix
    unsigned int       prefix16;    // selected top-16 bucket (0xFFFF sentinel when k==0)
    unsigned int       thresh_bits; // exact 32-bit threshold (bits of k-th largest)
    unsigned long long cnt_gt;      // count of values strictly > threshold
    double             sum_gt;      // sum of values strictly > threshold
};
__device__ State g_state;

// ---------------------------------------------------------------------------
// 0. init: zero histograms + state (runs every graph replay)
// ---------------------------------------------------------------------------
__global__ void init_kernel() {
    int i = blockIdx.x * blockDim.x + threadIdx.x;
    if (i < NBUCKET) { g_hist1[i] = 0u; g_hist2[i] = 0u; }
    if (i == 0) {
        g_state.num_pos    = 0ull;
        g_state.pos_ce_sum = 0.0;
        g_state.loc_sum    = 0.0;
        g_state.k          = 0ull;
        g_state.k_rem      = 0ull;
        g_state.cnt_above1 = 0ull;
        g_state.prefix16   = 0u;
        g_state.thresh_bits= 0xFFFFFFFFu;
        g_state.cnt_gt     = 0ull;
        g_state.sum_gt     = 0.0;
    }
}

// ---------------------------------------------------------------------------
// 1. main fused pass: CE, loc-L1, pos stats, ce_bits + top-16 histogram
//    256 threads/block, 256 anchors/block (NN/256 = 4366 blocks exactly)
// ---------------------------------------------------------------------------
__global__ __launch_bounds__(256) void main_kernel(
    const float* __restrict__ pred_loc,
    const float* __restrict__ pred_clf,
    const float* __restrict__ target_loc,
    const int*   __restrict__ target_cls)
{
    __shared__ float s_clf[256 * CC];       // 21504 B
    __shared__ float s_pce, s_pl1;
    __shared__ int   s_np;

    const int tid = threadIdx.x;
    const int a0  = blockIdx.x * 256;

    if (tid == 0) { s_pce = 0.f; s_pl1 = 0.f; s_np = 0; }

    // Coalesced float4 staging of 256*21 logits (block offset is 16B aligned:
    // 256*21*4 = 21504 bytes per block)
    {
        const float4* src = reinterpret_cast<const float4*>(pred_clf + (size_t)a0 * CC);
        float4*       dst = reinterpret_cast<float4*>(s_clf);
        #pragma unroll
        for (int j = tid; j < (256 * CC) / 4; j += 256) dst[j] = src[j];
    }
    __syncthreads();

    const int a    = a0 + tid;
    const int tcls = target_cls[a];
    const bool pos = (tcls != BACKGROUND);

    // log-softmax CE: bank-conflict-free (stride 21, gcd(21,32)=1)
    const float* x = s_clf + tid * CC;
    float mx = x[0];
    #pragma unroll
    for (int c = 1; c < CC; c++) mx = fmaxf(mx, x[c]);
    float se = 0.f;
    #pragma unroll
    for (int c = 0; c < CC; c++) se += __expf(x[c] - mx);
    float ce = mx + __logf(se) - x[tcls];
    ce = fmaxf(ce, 0.f);   // CE is >= 0 mathematically; guard rounding

    // negatives carry their CE bits; positives carry sentinel 0 (contributes
    // nothing to a top-k SUM, so tie handling stays exact)
    const unsigned int bits = pos ? 0u : __float_as_uint(ce);
    g_ce_bits[a] = bits;
    atomicAdd(&g_hist1[bits >> 16], 1u);

    // localization L1 (float4 coalesced)
    const float4 pl = reinterpret_cast<const float4*>(pred_loc)[a];
    const float4 tl = reinterpret_cast<const float4*>(target_loc)[a];
    const float l1 = fabsf(pl.x - tl.x) + fabsf(pl.y - tl.y)
                   + fabsf(pl.z - tl.z) + fabsf(pl.w - tl.w);

    float pce = pos ? ce : 0.f;
    float pl1 = pos ? l1 : 0.f;
    int   np  = pos ? 1  : 0;

    #pragma unroll
    for (int o = 16; o > 0; o >>= 1) {
        pce += __shfl_down_sync(0xFFFFFFFFu, pce, o);
        pl1 += __shfl_down_sync(0xFFFFFFFFu, pl1, o);
        np  += __shfl_down_sync(0xFFFFFFFFu, np,  o);
    }
    if ((tid & 31) == 0) {
        atomicAdd(&s_pce, pce);
        atomicAdd(&s_pl1, pl1);
        atomicAdd(&s_np,  np);
    }
    __syncthreads();
    if (tid == 0) {
        atomicAdd(&g_state.pos_ce_sum, (double)s_pce);
        atomicAdd(&g_state.loc_sum,    (double)s_pl1);
        atomicAdd(&g_state.num_pos,    (unsigned long long)s_np);
    }
}

// ---------------------------------------------------------------------------
// 2. scan1: single block (256 thr); pick top-16 prefix of k-th largest
// ---------------------------------------------------------------------------
__global__ __launch_bounds__(256) void scan1_kernel() {
    __shared__ unsigned long long chunk[256];
    __shared__ unsigned int       s_b[256];
    __shared__ int                s_sel;
    __shared__ unsigned long long s_above;
    __shared__ unsigned long long s_k;

    const int tid = threadIdx.x;

    unsigned long long s = 0;
    #pragma unroll 8
    for (int i = 0; i < 256; i++) s += (unsigned long long)g_hist1[tid * 256 + i];
    chunk[tid] = s;
    __syncthreads();

    if (tid == 0) {
        unsigned long long np   = g_state.num_pos;
        unsigned long long nneg = (unsigned long long)NN - np;
        unsigned long long k    = 3ull * np;
        if (k > nneg) k = nneg;
        g_state.k = k;
        s_k = k;
        if (k == 0ull) {
            s_sel = -1;
            g_state.prefix16   = 0xFFFFu;
            g_state.k_rem      = 0ull;
            g_state.cnt_above1 = 0ull;
        } else {
            unsigned long long above = 0; int sel = 0;
            for (int t = 255; t >= 0; t--) {
                if (above + chunk[t] >= k) { sel = t; break; }
                above += chunk[t];
            }
            s_sel = sel; s_above = above;
        }
    }
    __syncthreads();
    if (s_sel >= 0) s_b[tid] = g_hist1[s_sel * 256 + tid];
    __syncthreads();
    if (tid == 0 && s_sel >= 0) {
        unsigned long long run = s_above;
        int bb = s_sel * 256;
        for (int i = 255; i >= 0; i--) {
            unsigned long long c = (unsigned long long)s_b[i];
            if (run + c >= s_k) { bb = s_sel * 256 + i; break; }
            run += c;
        }
        g_state.prefix16   = (unsigned int)bb;
        g_state.cnt_above1 = run;
        g_state.k_rem      = s_k - run;
    }
}

// ---------------------------------------------------------------------------
// 3. hist2: pass over ce_bits; low-16 histogram within the selected prefix
// ---------------------------------------------------------------------------
__global__ __launch_bounds__(256) void hist2_kernel() {
    const unsigned int p = g_state.prefix16;
    const int i = blockIdx.x * blockDim.x + threadIdx.x;
    if (i < NN / 4) {
        uint4 v = reinterpret_cast<const uint4*>(g_ce_bits)[i];
        if ((v.x >> 16) == p) atomicAdd(&g_hist2[v.x & 0xFFFFu], 1u);
        if ((v.y >> 16) == p) atomicAdd(&g_hist2[v.y & 0xFFFFu], 1u);
        if ((v.z >> 16) == p) atomicAdd(&g_hist2[v.z & 0xFFFFu], 1u);
        if ((v.w >> 16) == p) atomicAdd(&g_hist2[v.w & 0xFFFFu], 1u);
    }
}

// ---------------------------------------------------------------------------
// 4. scan2: single block; exact 32-bit threshold + cnt_gt
// ---------------------------------------------------------------------------
__global__ __launch_bounds__(256) void scan2_kernel() {
    __shared__ unsigned long long chunk[256];
    __shared__ unsigned int       s_b[256];
    __shared__ int                s_sel;
    __shared__ unsigned long long s_above;
    __shared__ unsigned long long s_k;

    const int tid = threadIdx.x;

    unsigned long long s = 0;
    #pragma unroll 8
    for (int i = 0; i < 256; i++) s += (unsigned long long)g_hist2[tid * 256 + i];
    chunk[tid] = s;
    __syncthreads();

    if (tid == 0) {
        unsigned long long k = g_state.k_rem;
        s_k = k;
        if (k == 0ull) {      // k == 0 overall: no negatives taken
            s_sel = -1;
            g_state.thresh_bits = 0xFFFFFFFFu;
            g_state.cnt_gt      = 0ull;
        } else {
            unsigned long long above = 0; int sel = 0;
            for (int t = 255; t >= 0; t--) {
                if (above + chunk[t] >= k) { sel = t; break; }
                above += chunk[t];
            }
            s_sel = sel; s_above = above;
        }
    }
    __syncthreads();
    if (s_sel >= 0) s_b[tid] = g_hist2[s_sel * 256 + tid];
    __syncthreads();
    if (tid == 0 && s_sel >= 0) {
        unsigned long long run = s_above;
        int bb = s_sel * 256;
        for (int i = 255; i >= 0; i--) {
            unsigned long long c = (unsigned long long)s_b[i];
            if (run + c >= s_k) { bb = s_sel * 256 + i; break; }
            run += c;
        }
        g_state.thresh_bits = (g_state.prefix16 << 16) | (unsigned int)bb;
        g_state.cnt_gt      = g_state.cnt_above1 + run;
    }
}

// ---------------------------------------------------------------------------
// 5. sum pass: sum of values strictly greater than threshold (double)
// ---------------------------------------------------------------------------
__global__ __launch_bounds__(256) void sum_kernel() {
    const unsigned int T = g_state.thresh_bits;
    const int i = blockIdx.x * blockDim.x + threadIdx.x;
    double s = 0.0;
    if (i < NN / 4) {
        uint4 v = reinterpret_cast<const uint4*>(g_ce_bits)[i];
        if (v.x > T) s += (double)__uint_as_float(v.x);
        if (v.y > T) s += (double)__uint_as_float(v.y);
        if (v.z > T) s += (double)__uint_as_float(v.z);
        if (v.w > T) s += (double)__uint_as_float(v.w);
    }
    #pragma unroll
    for (int o = 16; o > 0; o >>= 1)
        s += __shfl_down_sync(0xFFFFFFFFu, s, o);
    __shared__ double sh[8];
    const int wid = threadIdx.x >> 5, lid = threadIdx.x & 31;
    if (lid == 0) sh[wid] = s;
    __syncthreads();
    if (threadIdx.x == 0) {
        double b = 0.0;
        #pragma unroll
        for (int w = 0; w < 8; w++) b += sh[w];
        atomicAdd(&g_state.sum_gt, b);
    }
}

// ---------------------------------------------------------------------------
// 6. finalize
// ---------------------------------------------------------------------------
__global__ void finalize_kernel(float* __restrict__ out) {
    const double np   = (double)g_state.num_pos;
    const double k    = (double)g_state.k;
    const unsigned long long ties = g_state.k - g_state.cnt_gt;
    const double tval = (ties > 0ull) ? (double)__uint_as_float(g_state.thresh_bits) : 0.0;
    const double topk = g_state.sum_gt + (double)ties * tval;
    out[0] = (float)((g_state.pos_ce_sum + topk) / (np + k));  // loss_cls
    out[1] = (float)(g_state.loc_sum / np);                    // loss_loc
}

// ---------------------------------------------------------------------------
// launch
// ---------------------------------------------------------------------------
extern "C" void kernel_launch(void* const* d_in, const int* in_sizes, int n_in,
                              void* d_out, int out_size)
{
    const float* pred_loc   = (const float*)d_in[0];
    const float* pred_clf   = (const float*)d_in[1];
    const float* target_loc = (const float*)d_in[2];
    const int*   target_cls = (const int*)  d_in[3];
    float* out = (float*)d_out;

    init_kernel<<<NBUCKET / 256, 256>>>();
    main_kernel<<<NN / 256, 256>>>(pred_loc, pred_clf, target_loc, target_cls);
    scan1_kernel<<<1, 256>>>();
    hist2_kernel<<<(NN / 4 + 255) / 256, 256>>>();
    scan2_kernel<<<1, 256>>>();
    sum_kernel<<<(NN / 4 + 255) / 256, 256>>>();
    finalize_kernel<<<1, 1>>>(out);
}

// round 2
// speedup vs baseline: 4.7348x; 4.7348x over previous
#include <cuda_runtime.h>
#include <cstdint>

// Problem constants
#define BB 128
#define AA 8732
#define NN (BB * AA)          // 1,117,696 = 256 * 4366
#define CC 21
#define NBLK_MAIN (NN / 256)  // 4366
#define N4 (NN / 4)           // 279,424 uint4 elements
#define BACKGROUND 0
#define PASS_GRID 296         // 2 blocks per SM on 148-SM B200

// ---------------------------------------------------------------------------
// Device scratch (no allocations allowed)
// ---------------------------------------------------------------------------
__device__ unsigned int g_ce_bits[NN];
__device__ unsigned int g_h1[4096];   // top 12 bits
__device__ unsigned int g_h2[4096];   // bits [19:8] within p1
__device__ unsigned int g_h3[256];    // bits [7:0]  within p1:p2
__device__ float4       g_part[NBLK_MAIN]; // (pos_ce, pos_l1, num_pos, 0) per block

struct State {
    double pos_ce_sum, loc_sum, sum_gt;
    unsigned long long num_pos, k, k_rem, cnt_above, cnt_gt;
    unsigned int p1, p2, thresh_bits;
};
__device__ State g_state;

// ---------------------------------------------------------------------------
// 0. init: zero histograms + state (every graph replay)
// ---------------------------------------------------------------------------
__global__ void init_kernel() {
    int i = blockIdx.x * blockDim.x + threadIdx.x;
    if (i < 4096) { g_h1[i] = 0u; g_h2[i] = 0u; }
    if (i < 256)  g_h3[i] = 0u;
    if (i == 0) {
        g_state.pos_ce_sum = 0.0; g_state.loc_sum = 0.0; g_state.sum_gt = 0.0;
        g_state.num_pos = 0ull; g_state.k = 0ull; g_state.k_rem = 0ull;
        g_state.cnt_above = 0ull; g_state.cnt_gt = 0ull;
        g_state.p1 = 0xFFFFFFFFu; g_state.p2 = 0xFFFFFFFFu;
        g_state.thresh_bits = 0xFFFFFFFFu;
    }
}

// ---------------------------------------------------------------------------
// 1. main fused pass: CE, loc-L1, ce_bits store, per-block partial stats.
//    NO global atomics.
// ---------------------------------------------------------------------------
__global__ __launch_bounds__(256) void main_kernel(
    const float* __restrict__ pred_loc,
    const float* __restrict__ pred_clf,
    const float* __restrict__ target_loc,
    const int*   __restrict__ target_cls)
{
    __shared__ float s_clf[256 * CC];       // 21504 B
    __shared__ float s_pce, s_pl1;
    __shared__ int   s_np;

    const int tid = threadIdx.x;
    const int a0  = blockIdx.x * 256;

    if (tid == 0) { s_pce = 0.f; s_pl1 = 0.f; s_np = 0; }

    // Coalesced float4 staging of 256*21 logits (block offset 16B aligned)
    {
        const float4* src = reinterpret_cast<const float4*>(pred_clf + (size_t)a0 * CC);
        float4*       dst = reinterpret_cast<float4*>(s_clf);
        #pragma unroll
        for (int j = tid; j < (256 * CC) / 4; j += 256) dst[j] = src[j];
    }
    __syncthreads();

    const int a    = a0 + tid;
    const int tcls = target_cls[a];
    const bool pos = (tcls != BACKGROUND);

    // log-softmax CE (stride-21 shared reads, gcd(21,32)=1 -> conflict-free)
    const float* x = s_clf + tid * CC;
    float mx = x[0];
    #pragma unroll
    for (int c = 1; c < CC; c++) mx = fmaxf(mx, x[c]);
    float se = 0.f;
    #pragma unroll
    for (int c = 0; c < CC; c++) se += __expf(x[c] - mx);
    float ce = mx + __logf(se) - x[tcls];
    ce = fmaxf(ce, 0.f);

    // negatives carry CE bits; positives carry sentinel 0 (adds 0 to a top-k sum)
    g_ce_bits[a] = pos ? 0u : __float_as_uint(ce);

    // localization L1
    const float4 pl = reinterpret_cast<const float4*>(pred_loc)[a];
    const float4 tl = reinterpret_cast<const float4*>(target_loc)[a];
    const float l1 = fabsf(pl.x - tl.x) + fabsf(pl.y - tl.y)
                   + fabsf(pl.z - tl.z) + fabsf(pl.w - tl.w);

    float pce = pos ? ce : 0.f;
    float pl1 = pos ? l1 : 0.f;
    int   np  = pos ? 1  : 0;
    #pragma unroll
    for (int o = 16; o > 0; o >>= 1) {
        pce += __shfl_down_sync(0xFFFFFFFFu, pce, o);
        pl1 += __shfl_down_sync(0xFFFFFFFFu, pl1, o);
        np  += __shfl_down_sync(0xFFFFFFFFu, np,  o);
    }
    if ((tid & 31) == 0) {
        atomicAdd(&s_pce, pce);
        atomicAdd(&s_pl1, pl1);
        atomicAdd(&s_np,  np);
    }
    __syncthreads();
    if (tid == 0) g_part[blockIdx.x] = make_float4(s_pce, s_pl1, (float)s_np, 0.f);
}

// ---------------------------------------------------------------------------
// 2. hist1: top-12-bit histogram, shared-privatized, nonzero flush
// ---------------------------------------------------------------------------
__global__ __launch_bounds__(256) void hist1_kernel() {
    __shared__ unsigned int h[4096];
    for (int j = threadIdx.x; j < 4096; j += 256) h[j] = 0u;
    __syncthreads();
    const int stride = gridDim.x * blockDim.x;
    for (int i = blockIdx.x * blockDim.x + threadIdx.x; i < N4; i += stride) {
        uint4 v = reinterpret_cast<const uint4*>(g_ce_bits)[i];
        atomicAdd(&h[v.x >> 20], 1u);
        atomicAdd(&h[v.y >> 20], 1u);
        atomicAdd(&h[v.z >> 20], 1u);
        atomicAdd(&h[v.w >> 20], 1u);
    }
    __syncthreads();
    for (int j = threadIdx.x; j < 4096; j += 256) {
        unsigned int c = h[j];
        if (c) atomicAdd(&g_h1[j], c);
    }
}

// ---------------------------------------------------------------------------
// 3/5/7. scan: descending radix-select step. level 1 also reduces partials.
// ---------------------------------------------------------------------------
__global__ __launch_bounds__(256) void scan_kernel(int level) {
    __shared__ unsigned long long chunk[256];
    __shared__ double sa[256], sb[256];
    __shared__ unsigned long long sc[256];

    const int tid = threadIdx.x;

    if (level == 1) {
        double dce = 0.0, dl1 = 0.0; unsigned long long np = 0;
        for (int i = tid; i < NBLK_MAIN; i += 256) {
            float4 p = g_part[i];
            dce += (double)p.x; dl1 += (double)p.y; np += (unsigned long long)p.z;
        }
        sa[tid] = dce; sb[tid] = dl1; sc[tid] = np;
    }

    const unsigned int* hist = (level == 1) ? g_h1 : (level == 2) ? g_h2 : g_h3;
    const int stride = (level == 3) ? 1 : 16;

    unsigned long long s = 0;
    for (int j = 0; j < stride; j++) s += (unsigned long long)hist[tid * stride + j];
    chunk[tid] = s;
    __syncthreads();

    if (tid == 0) {
        if (level == 1) {
            double dce = 0.0, dl1 = 0.0; unsigned long long np = 0;
            for (int i = 0; i < 256; i++) { dce += sa[i]; dl1 += sb[i]; np += sc[i]; }
            g_state.pos_ce_sum = dce;
            g_state.loc_sum    = dl1;
            g_state.num_pos    = np;
            unsigned long long nneg = (unsigned long long)NN - np;
            unsigned long long k = 3ull * np;
            if (k > nneg) k = nneg;
            g_state.k = k;
            g_state.k_rem = k;
            g_state.cnt_above = 0ull;
        }
        unsigned long long k = g_state.k_rem;
        if (k == 0ull) {
            // only possible when overall k == 0; sentinels already in state
            if (level == 3) { g_state.thresh_bits = 0xFFFFFFFFu; g_state.cnt_gt = 0ull; }
        } else {
            unsigned long long above = 0; int sel = 255;
            for (int t = 255; t >= 0; t--) {
                if (above + chunk[t] >= k) { sel = t; break; }
                above += chunk[t];
            }
            int b = sel * stride;
            for (int j = stride - 1; j >= 0; j--) {
                unsigned long long c = (unsigned long long)hist[sel * stride + j];
                if (above + c >= k) { b = sel * stride + j; break; }
                above += c;
            }
            g_state.cnt_above += above;
            g_state.k_rem = k - above;   // >= 1 by construction
            if (level == 1)      g_state.p1 = (unsigned int)b;
            else if (level == 2) g_state.p2 = (unsigned int)b;
            else {
                g_state.thresh_bits = (g_state.p1 << 20) | (g_state.p2 << 8) | (unsigned int)b;
                g_state.cnt_gt = g_state.cnt_above;
            }
        }
    }
}

// ---------------------------------------------------------------------------
// 4. refine1: bits[19:8] histogram within top-12 prefix p1
// ---------------------------------------------------------------------------
__global__ __launch_bounds__(256) void refine1_kernel() {
    __shared__ unsigned int h[4096];
    for (int j = threadIdx.x; j < 4096; j += 256) h[j] = 0u;
    __syncthreads();
    const unsigned int p1 = g_state.p1;  // sentinel 0xFFFFFFFF matches nothing
    const int stride = gridDim.x * blockDim.x;
    for (int i = blockIdx.x * blockDim.x + threadIdx.x; i < N4; i += stride) {
        uint4 v = reinterpret_cast<const uint4*>(g_ce_bits)[i];
        if ((v.x >> 20) == p1) atomicAdd(&h[(v.x >> 8) & 0xFFFu], 1u);
        if ((v.y >> 20) == p1) atomicAdd(&h[(v.y >> 8) & 0xFFFu], 1u);
        if ((v.z >> 20) == p1) atomicAdd(&h[(v.z >> 8) & 0xFFFu], 1u);
        if ((v.w >> 20) == p1) atomicAdd(&h[(v.w >> 8) & 0xFFFu], 1u);
    }
    __syncthreads();
    for (int j = threadIdx.x; j < 4096; j += 256) {
        unsigned int c = h[j];
        if (c) atomicAdd(&g_h2[j], c);
    }
}

// ---------------------------------------------------------------------------
// 6. refine2: bits[7:0] histogram within 24-bit prefix p1:p2
// ---------------------------------------------------------------------------
__global__ __launch_bounds__(256) void refine2_kernel() {
    __shared__ unsigned int h[256];
    if (threadIdx.x < 256) h[threadIdx.x] = 0u;
    __syncthreads();
    const unsigned int p20 = (g_state.p1 << 12) | g_state.p2; // sentinel-safe
    const int stride = gridDim.x * blockDim.x;
    for (int i = blockIdx.x * blockDim.x + threadIdx.x; i < N4; i += stride) {
        uint4 v = reinterpret_cast<const uint4*>(g_ce_bits)[i];
        if ((v.x >> 8) == p20) atomicAdd(&h[v.x & 0xFFu], 1u);
        if ((v.y >> 8) == p20) atomicAdd(&h[v.y & 0xFFu], 1u);
        if ((v.z >> 8) == p20) atomicAdd(&h[v.z & 0xFFu], 1u);
        if ((v.w >> 8) == p20) atomicAdd(&h[v.w & 0xFFu], 1u);
    }
    __syncthreads();
    if (threadIdx.x < 256) {
        unsigned int c = h[threadIdx.x];
        if (c) atomicAdd(&g_h3[threadIdx.x], c);
    }
}

// ---------------------------------------------------------------------------
// 8. sum pass: sum of values strictly greater than threshold
// ---------------------------------------------------------------------------
__global__ __launch_bounds__(256) void sum_kernel() {
    const unsigned int T = g_state.thresh_bits;
    const int stride = gridDim.x * blockDim.x;
    double s = 0.0;
    for (int i = blockIdx.x * blockDim.x + threadIdx.x; i < N4; i += stride) {
        uint4 v = reinterpret_cast<const uint4*>(g_ce_bits)[i];
        if (v.x > T) s += (double)__uint_as_float(v.x);
        if (v.y > T) s += (double)__uint_as_float(v.y);
        if (v.z > T) s += (double)__uint_as_float(v.z);
        if (v.w > T) s += (double)__uint_as_float(v.w);
    }
    #pragma unroll
    for (int o = 16; o > 0; o >>= 1)
        s += __shfl_down_sync(0xFFFFFFFFu, s, o);
    __shared__ double sh[8];
    const int wid = threadIdx.x >> 5, lid = threadIdx.x & 31;
    if (lid == 0) sh[wid] = s;
    __syncthreads();
    if (threadIdx.x == 0) {
        double b = 0.0;
        #pragma unroll
        for (int w = 0; w < 8; w++) b += sh[w];
        atomicAdd(&g_state.sum_gt, b);   // 296 atomics total: negligible
    }
}

// ---------------------------------------------------------------------------
// 9. finalize
// ---------------------------------------------------------------------------
__global__ void finalize_kernel(float* __restrict__ out) {
    const double np = (double)g_state.num_pos;
    const double k  = (double)g_state.k;
    const unsigned long long ties = g_state.k - g_state.cnt_gt;
    const double tval = (ties > 0ull) ? (double)__uint_as_float(g_state.thresh_bits) : 0.0;
    const double topk = g_state.sum_gt + (double)ties * tval;
    out[0] = (float)((g_state.pos_ce_sum + topk) / (np + k));  // loss_cls
    out[1] = (float)(g_state.loc_sum / np);                    // loss_loc
}

// ---------------------------------------------------------------------------
// launch
// ---------------------------------------------------------------------------
extern "C" void kernel_launch(void* const* d_in, const int* in_sizes, int n_in,
                              void* d_out, int out_size)
{
    const float* pred_loc   = (const float*)d_in[0];
    const float* pred_clf   = (const float*)d_in[1];
    const float* target_loc = (const float*)d_in[2];
    const int*   target_cls = (const int*)  d_in[3];
    float* out = (float*)d_out;

    init_kernel<<<16, 256>>>();
    main_kernel<<<NBLK_MAIN, 256>>>(pred_loc, pred_clf, target_loc, target_cls);
    hist1_kernel<<<PASS_GRID, 256>>>();
    scan_kernel<<<1, 256>>>(1);
    refine1_kernel<<<PASS_GRID, 256>>>();
    scan_kernel<<<1, 256>>>(2);
    refine2_kernel<<<PASS_GRID, 256>>>();
    scan_kernel<<<1, 256>>>(3);
    sum_kernel<<<PASS_GRID, 256>>>();
    finalize_kernel<<<1, 1>>>(out);
}

// round 5
// speedup vs baseline: 5.3258x; 1.1248x over previous
#include <cuda_runtime.h>
#include <cstdint>

// Problem constants
#define BB 128
#define AA 8732
#define NN (BB * AA)          // 1,117,696 = 256 * 4366
#define CC 21
#define NBLK_MAIN (NN / 256)  // 4366
#define N4 (NN / 4)
#define BACKGROUND 0
#define PASS_GRID 296

// ---------------------------------------------------------------------------
// Device scratch (static zero-init; re-zeroed at the end of every run)
// ---------------------------------------------------------------------------
__device__ unsigned int g_ce_bits[NN];
__device__ unsigned int g_h1[4096];   // top 12 bits
__device__ unsigned int g_h2[4096];   // bits [19:8] within p1
__device__ unsigned int g_h3[256];    // bits [7:0]  within 24-bit prefix
__device__ double       g_s3[256];    // per-bucket value sums within prefix
__device__ unsigned int g_ctr[3];     // last-block tickets: main, r1, r2

struct State {
    double pos_ce_sum, loc_sum, sum_gt_pre;   // sum of values with (v>>8) > p24
    unsigned long long num_pos, k, k_rem, cnt_above;
    unsigned int p1;
};
__device__ State g_state;             // zero-init

// ---------------------------------------------------------------------------
// Parallel descending radix-select over a histogram (block-wide, result
// broadcast). Precondition: 1 <= k <= total count in hist.
// ---------------------------------------------------------------------------
template<int BPT>   // buckets per thread (256*BPT buckets total)
__device__ void radix_select(const unsigned int* __restrict__ hist,
                             unsigned long long k,
                             unsigned int& b_out, unsigned long long& above_out)
{
    __shared__ unsigned int ssum[256];
    __shared__ unsigned int s_b;
    __shared__ unsigned long long s_above;
    const int t = threadIdx.x;

    unsigned int cnt[BPT];
    unsigned int tsum = 0;
    #pragma unroll
    for (int j = 0; j < BPT; j++) { cnt[j] = hist[t * BPT + j]; tsum += cnt[j]; }
    ssum[t] = tsum;
    __syncthreads();
    // inclusive suffix scan (high buckets first == descending values)
    for (int o = 1; o < 256; o <<= 1) {
        unsigned int v = ssum[t] + ((t + o < 256) ? ssum[t + o] : 0u);
        __syncthreads();
        ssum[t] = v;
        __syncthreads();
    }
    unsigned long long incl  = ssum[t];
    unsigned long long above = (t < 255) ? (unsigned long long)ssum[t + 1] : 0ull;
    if (above < k && incl >= k) {           // exactly one owner thread
        unsigned long long a = above;
        int b = t * BPT;
        #pragma unroll
        for (int j = BPT - 1; j >= 0; j--) {
            unsigned long long c = cnt[j];
            if (a + c >= k) { b = t * BPT + j; break; }
            a += c;
        }
        s_b = (unsigned int)b;
        s_above = a;
    }
    __syncthreads();
    b_out = s_b;
    above_out = s_above;
}

// ---------------------------------------------------------------------------
// 1. main fused pass: CE, loc-L1, ce_bits store, inline 12-bit hist,
//    per-block stats; last block computes k and selects p1.
// ---------------------------------------------------------------------------
__global__ __launch_bounds__(256) void main_kernel(
    const float* __restrict__ pred_loc,
    const float* __restrict__ pred_clf,
    const float* __restrict__ target_loc,
    const int*   __restrict__ target_cls)
{
    __shared__ float s_clf[256 * CC];        // 21504 B
    __shared__ unsigned int s_h[4096];       // 16384 B
    __shared__ float s_pce, s_pl1;
    __shared__ int   s_np;
    __shared__ int   s_last;
    __shared__ unsigned long long s_k;

    const int tid = threadIdx.x;
    const int a0  = blockIdx.x * 256;

    if (tid == 0) { s_pce = 0.f; s_pl1 = 0.f; s_np = 0; }
    for (int j = tid; j < 4096; j += 256) s_h[j] = 0u;

    {
        const float4* src = reinterpret_cast<const float4*>(pred_clf + (size_t)a0 * CC);
        float4*       dst = reinterpret_cast<float4*>(s_clf);
        #pragma unroll
        for (int j = tid; j < (256 * CC) / 4; j += 256) dst[j] = src[j];
    }
    __syncthreads();

    const int a    = a0 + tid;
    const int tcls = target_cls[a];
    const bool pos = (tcls != BACKGROUND);

    // log-softmax CE (stride-21 shared reads: gcd(21,32)=1 -> conflict-free)
    const float* x = s_clf + tid * CC;
    float mx = x[0];
    #pragma unroll
    for (int c = 1; c < CC; c++) mx = fmaxf(mx, x[c]);
    float se = 0.f;
    #pragma unroll
    for (int c = 0; c < CC; c++) se += __expf(x[c] - mx);
    float ce = mx + __logf(se) - x[tcls];
    ce = fmaxf(ce, 0.f);

    // negatives carry CE bits; positives carry 0 (adds nothing to a top-k sum)
    const unsigned int bits = pos ? 0u : __float_as_uint(ce);
    g_ce_bits[a] = bits;
    atomicAdd(&s_h[bits >> 20], 1u);

    const float4 pl = reinterpret_cast<const float4*>(pred_loc)[a];
    const float4 tl = reinterpret_cast<const float4*>(target_loc)[a];
    const float l1 = fabsf(pl.x - tl.x) + fabsf(pl.y - tl.y)
                   + fabsf(pl.z - tl.z) + fabsf(pl.w - tl.w);

    float pce = pos ? ce : 0.f;
    float pl1 = pos ? l1 : 0.f;
    int   np  = pos ? 1  : 0;
    #pragma unroll
    for (int o = 16; o > 0; o >>= 1) {
        pce += __shfl_down_sync(0xFFFFFFFFu, pce, o);
        pl1 += __shfl_down_sync(0xFFFFFFFFu, pl1, o);
        np  += __shfl_down_sync(0xFFFFFFFFu, np,  o);
    }
    if ((tid & 31) == 0) {
        atomicAdd(&s_pce, pce);
        atomicAdd(&s_pl1, pl1);
        atomicAdd(&s_np,  np);
    }
    __syncthreads();

    for (int j = tid; j < 4096; j += 256) {
        unsigned int c = s_h[j];
        if (c) atomicAdd(&g_h1[j], c);
    }
    if (tid == 0) {
        atomicAdd(&g_state.pos_ce_sum, (double)s_pce);
        atomicAdd(&g_state.loc_sum,    (double)s_pl1);
        atomicAdd(&g_state.num_pos,    (unsigned long long)s_np);
        __threadfence();
        unsigned int prev = atomicAdd(&g_ctr[0], 1u);
        s_last = (prev == (unsigned int)gridDim.x - 1u);
    }
    __syncthreads();
    if (!s_last) return;

    // ---- last block: compute k, select top-12 prefix p1 ----
    if (tid == 0) {
        unsigned long long npos = g_state.num_pos;
        unsigned long long nneg = (unsigned long long)NN - npos;
        unsigned long long k = 3ull * npos;
        if (k > nneg) k = nneg;
        g_state.k = k;
        s_k = k;
    }
    __syncthreads();
    if (s_k == 0ull) {
        if (tid == 0) { g_state.p1 = 0xFFFFFFFFu; g_state.k_rem = 0ull; g_state.cnt_above = 0ull; }
        return;
    }
    unsigned int b; unsigned long long above;
    radix_select<16>(g_h1, s_k, b, above);
    if (tid == 0) {
        g_state.p1 = b;
        g_state.cnt_above = above;
        g_state.k_rem = s_k - above;   // >= 1
    }
}

// ---------------------------------------------------------------------------
// 2. refine1: bits[19:8] hist within p1; last block extends prefix to 24 bits
// ---------------------------------------------------------------------------
__global__ __launch_bounds__(256) void refine1_kernel() {
    __shared__ unsigned int s_h[4096];
    __shared__ int s_last;
    const int tid = threadIdx.x;
    for (int j = tid; j < 4096; j += 256) s_h[j] = 0u;
    __syncthreads();

    const unsigned int p1 = g_state.p1;     // sentinel matches nothing
    const int stride = gridDim.x * blockDim.x;
    for (int i = blockIdx.x * blockDim.x + tid; i < N4; i += stride) {
        uint4 v = reinterpret_cast<const uint4*>(g_ce_bits)[i];
        if ((v.x >> 20) == p1) atomicAdd(&s_h[(v.x >> 8) & 0xFFFu], 1u);
        if ((v.y >> 20) == p1) atomicAdd(&s_h[(v.y >> 8) & 0xFFFu], 1u);
        if ((v.z >> 20) == p1) atomicAdd(&s_h[(v.z >> 8) & 0xFFFu], 1u);
        if ((v.w >> 20) == p1) atomicAdd(&s_h[(v.w >> 8) & 0xFFFu], 1u);
    }
    __syncthreads();
    for (int j = tid; j < 4096; j += 256) {
        unsigned int c = s_h[j];
        if (c) atomicAdd(&g_h2[j], c);
    }
    if (tid == 0) {
        __threadfence();
        unsigned int prev = atomicAdd(&g_ctr[1], 1u);
        s_last = (prev == (unsigned int)gridDim.x - 1u);
    }
    __syncthreads();
    if (!s_last) return;

    unsigned long long kr = g_state.k_rem;
    if (kr == 0ull) return;                  // k==0: sentinel prefix stays
    unsigned int b; unsigned long long above;
    radix_select<16>(g_h2, kr, b, above);
    if (tid == 0) {
        g_state.p1 = (g_state.p1 << 12) | b; // 24-bit prefix
        g_state.cnt_above += above;
        g_state.k_rem = kr - above;
    }
}

// ---------------------------------------------------------------------------
// 3. refine2 + sum + finalize + re-zero.
//    One pass: low-8 counts AND double sums for prefix-equal elements,
//    plus running sum of strictly-above-prefix elements.
// ---------------------------------------------------------------------------
__global__ __launch_bounds__(256) void final_kernel(float* __restrict__ out) {
    __shared__ unsigned int s_h[256];
    __shared__ double s_s[256];
    __shared__ double sh[8];
    __shared__ int s_last;
    const int tid = threadIdx.x;
    s_h[tid] = 0u;
    s_s[tid] = 0.0;
    __syncthreads();

    const unsigned int p24 = g_state.p1;    // 24-bit prefix (or sentinel)
    const int stride = gridDim.x * blockDim.x;
    double gt = 0.0;                        // values with (v>>8) > p24
    for (int i = blockIdx.x * blockDim.x + tid; i < N4; i += stride) {
        uint4 v = reinterpret_cast<const uint4*>(g_ce_bits)[i];
        unsigned int hx = v.x >> 8, hy = v.y >> 8, hz = v.z >> 8, hw = v.w >> 8;
        if (hx > p24) gt += (double)__uint_as_float(v.x);
        else if (hx == p24) { atomicAdd(&s_h[v.x & 0xFFu], 1u); atomicAdd(&s_s[v.x & 0xFFu], (double)__uint_as_float(v.x)); }
        if (hy > p24) gt += (double)__uint_as_float(v.y);
        else if (hy == p24) { atomicAdd(&s_h[v.y & 0xFFu], 1u); atomicAdd(&s_s[v.y & 0xFFu], (double)__uint_as_float(v.y)); }
        if (hz > p24) gt += (double)__uint_as_float(v.z);
        else if (hz == p24) { atomicAdd(&s_h[v.z & 0xFFu], 1u); atomicAdd(&s_s[v.z & 0xFFu], (double)__uint_as_float(v.z)); }
        if (hw > p24) gt += (double)__uint_as_float(v.w);
        else if (hw == p24) { atomicAdd(&s_h[v.w & 0xFFu], 1u); atomicAdd(&s_s[v.w & 0xFFu], (double)__uint_as_float(v.w)); }
    }
    // reduce gt within block
    #pragma unroll
    for (int o = 16; o > 0; o >>= 1)
        gt += __shfl_down_sync(0xFFFFFFFFu, gt, o);
    const int wid = tid >> 5, lid = tid & 31;
    if (lid == 0) sh[wid] = gt;
    __syncthreads();
    // flush shared hist/sums
    {
        unsigned int c = s_h[tid];
        if (c) { atomicAdd(&g_h3[tid], c); atomicAdd(&g_s3[tid], s_s[tid]); }
    }
    if (tid == 0) {
        double b = 0.0;
        #pragma unroll
        for (int w = 0; w < 8; w++) b += sh[w];
        atomicAdd(&g_state.sum_gt_pre, b);
        __threadfence();
        unsigned int prev = atomicAdd(&g_ctr[2], 1u);
        s_last = (prev == (unsigned int)gridDim.x - 1u);
    }
    __syncthreads();
    if (!s_last) goto done;

    {
        const unsigned long long kr = g_state.k_rem;
        const double np = (double)g_state.num_pos;
        const double kk = (double)g_state.k;

        if (kr == 0ull) {     // k == 0 overall: topk = 0 (matches reference 0/0)
            if (tid == 0) {
                out[0] = (float)(g_state.pos_ce_sum / (np + kk));
                out[1] = (float)(g_state.loc_sum / np);
            }
        } else {
            unsigned int b; unsigned long long above;
            radix_select<1>(g_h3, kr, b, above);
            // parallel sum of bucket sums strictly above b
            double tail = (tid > (int)b) ? g_s3[tid] : 0.0;
            #pragma unroll
            for (int o = 16; o > 0; o >>= 1)
                tail += __shfl_down_sync(0xFFFFFFFFu, tail, o);
            if (lid == 0) sh[wid] = tail;
            __syncthreads();
            if (tid == 0) {
                double t2 = 0.0;
                #pragma unroll
                for (int w = 0; w < 8; w++) t2 += sh[w];
                const unsigned int thresh = (g_state.p1 << 8) | b;
                const unsigned long long cnt_gt = g_state.cnt_above + above;
                const unsigned long long ties = g_state.k - cnt_gt;
                const double tval = (double)__uint_as_float(thresh);
                const double topk = g_state.sum_gt_pre + t2 + (double)ties * tval;
                out[0] = (float)((g_state.pos_ce_sum + topk) / (np + kk));
                out[1] = (float)(g_state.loc_sum / np);
            }
        }
    }
    __syncthreads();
    // re-zero scratch for the next graph replay
    for (int j = tid; j < 4096; j += 256) { g_h1[j] = 0u; g_h2[j] = 0u; }
    g_h3[tid] = 0u;
    g_s3[tid] = 0.0;
    if (tid < 3) g_ctr[tid] = 0u;
    if (tid == 0) {
        g_state.pos_ce_sum = 0.0; g_state.loc_sum = 0.0; g_state.sum_gt_pre = 0.0;
        g_state.num_pos = 0ull; g_state.k = 0ull; g_state.k_rem = 0ull;
        g_state.cnt_above = 0ull;
        g_state.p1 = 0xFFFFFFFFu;
    }
done: ;
}

// ---------------------------------------------------------------------------
// launch: 3 kernels total
// ---------------------------------------------------------------------------
extern "C" void kernel_launch(void* const* d_in, const int* in_sizes, int n_in,
                              void* d_out, int out_size)
{
    const float* pred_loc   = (const float*)d_in[0];
    const float* pred_clf   = (const float*)d_in[1];
    const float* target_loc = (const float*)d_in[2];
    const int*   target_cls = (const int*)  d_in[3];
    float* out = (float*)d_out;

    main_kernel<<<NBLK_MAIN, 256>>>(pred_loc, pred_clf, target_loc, target_cls);
    refine1_kernel<<<PASS_GRID, 256>>>();
    final_kernel<<<PASS_GRID, 256>>>(out);
}

// round 7
// speedup vs baseline: 5.5707x; 1.0460x over previous
#include <cuda_runtime.h>
#include <cstdint>

// Problem constants
#define BB 128
#define AA 8732
#define NN (BB * AA)          // 1,117,696 = 256 * 4366
#define CC 21
#define NTILES (NN / 256)     // 4366
#define TILES_PER_BLK 8
#define NBLK_MAIN ((NTILES + TILES_PER_BLK - 1) / TILES_PER_BLK)  // 546
#define N4 (NN / 4)
#define BACKGROUND 0
#define PASS_GRID 296

// ---------------------------------------------------------------------------
// Device scratch (static zero-init; re-zeroed at the end of every run)
// Radix levels: L1 = bits[31:24] (256), L2 = bits[23:12] (4096), L3 = bits[11:0] (4096)
// ---------------------------------------------------------------------------
__device__ unsigned int g_ce_bits[NN];
__device__ unsigned int g_h1[256];
__device__ unsigned int g_h2[4096];
__device__ unsigned int g_h3[4096];
__device__ unsigned int g_ctr[3];     // last-block tickets: main, r1, final

struct State {
    double pos_ce_sum, loc_sum, sum_gt_pre;  // sum over (v>>12) > p20
    unsigned long long num_pos, k, k_rem, cnt_above;
    unsigned int p1;                          // evolving prefix (8 -> 20 bits)
};
__device__ State g_state;             // zero-init

// ---------------------------------------------------------------------------
// Parallel descending radix-select over a histogram (block-wide broadcast).
// Precondition: 1 <= k <= total count in hist.
// ---------------------------------------------------------------------------
template<int BPT>
__device__ void radix_select(const unsigned int* __restrict__ hist,
                             unsigned long long k,
                             unsigned int& b_out, unsigned long long& above_out)
{
    __shared__ unsigned int ssum[256];
    __shared__ unsigned int s_b;
    __shared__ unsigned long long s_above;
    const int t = threadIdx.x;

    unsigned int cnt[BPT];
    unsigned int tsum = 0;
    #pragma unroll
    for (int j = 0; j < BPT; j++) { cnt[j] = hist[t * BPT + j]; tsum += cnt[j]; }
    ssum[t] = tsum;
    __syncthreads();
    for (int o = 1; o < 256; o <<= 1) {   // inclusive suffix scan (descending)
        unsigned int v = ssum[t] + ((t + o < 256) ? ssum[t + o] : 0u);
        __syncthreads();
        ssum[t] = v;
        __syncthreads();
    }
    unsigned long long incl  = ssum[t];
    unsigned long long above = (t < 255) ? (unsigned long long)ssum[t + 1] : 0ull;
    if (above < k && incl >= k) {         // exactly one owner thread
        unsigned long long a = above;
        int b = t * BPT;
        #pragma unroll
        for (int j = BPT - 1; j >= 0; j--) {
            unsigned long long c = cnt[j];
            if (a + c >= k) { b = t * BPT + j; break; }
            a += c;
        }
        s_b = (unsigned int)b;
        s_above = a;
    }
    __syncthreads();
    b_out = s_b;
    above_out = s_above;
}

// ---------------------------------------------------------------------------
// 1. main fused pass: 8 tiles/block. CE, loc-L1, ce_bits, 256-bucket L1 hist
//    (warp-aggregated), register-accumulated stats; last block selects p1.
// ---------------------------------------------------------------------------
__global__ __launch_bounds__(256) void main_kernel(
    const float* __restrict__ pred_loc,
    const float* __restrict__ pred_clf,
    const float* __restrict__ target_loc,
    const int*   __restrict__ target_cls)
{
    __shared__ float s_clf[256 * CC];        // 21504 B
    __shared__ unsigned int s_h[256];        // 1024 B
    __shared__ float s_pce, s_pl1;
    __shared__ int   s_np;
    __shared__ int   s_last;
    __shared__ unsigned long long s_k;

    const int tid = threadIdx.x;
    const int lane = tid & 31;

    if (tid == 0) { s_pce = 0.f; s_pl1 = 0.f; s_np = 0; }
    s_h[tid] = 0u;

    float pce_acc = 0.f, pl1_acc = 0.f;
    int np_acc = 0;

    const int tile0 = blockIdx.x * TILES_PER_BLK;
    for (int t = 0; t < TILES_PER_BLK; t++) {
        const int tile = tile0 + t;
        if (tile >= NTILES) break;
        const int a0 = tile * 256;

        __syncthreads();     // s_clf reuse: previous tile's readers done
        {
            const float4* src = reinterpret_cast<const float4*>(pred_clf + (size_t)a0 * CC);
            float4*       dst = reinterpret_cast<float4*>(s_clf);
            #pragma unroll
            for (int j = tid; j < (256 * CC) / 4; j += 256) dst[j] = src[j];
        }
        __syncthreads();

        const int a    = a0 + tid;
        const int tcls = target_cls[a];
        const bool pos = (tcls != BACKGROUND);

        // log-softmax CE (stride-21 shared reads: gcd(21,32)=1 -> conflict-free)
        const float* x = s_clf + tid * CC;
        float mx = x[0];
        #pragma unroll
        for (int c = 1; c < CC; c++) mx = fmaxf(mx, x[c]);
        float se = 0.f;
        #pragma unroll
        for (int c = 0; c < CC; c++) se += __expf(x[c] - mx);
        float ce = mx + __logf(se) - x[tcls];
        ce = fmaxf(ce, 0.f);

        // negatives carry CE bits; positives carry 0 (adds 0 to any top-k sum)
        const unsigned int bits = pos ? 0u : __float_as_uint(ce);
        g_ce_bits[a] = bits;

        // warp-aggregated 256-bucket histogram update (CE clusters -> hot bucket)
        {
            const unsigned int bkt = bits >> 24;
            unsigned int mask = __match_any_sync(0xFFFFFFFFu, bkt);
            if ((int)(__ffs(mask) - 1) == lane)
                atomicAdd(&s_h[bkt], (unsigned int)__popc(mask));
        }

        const float4 pl = reinterpret_cast<const float4*>(pred_loc)[a];
        const float4 tl = reinterpret_cast<const float4*>(target_loc)[a];
        const float l1 = fabsf(pl.x - tl.x) + fabsf(pl.y - tl.y)
                       + fabsf(pl.z - tl.z) + fabsf(pl.w - tl.w);

        if (pos) { pce_acc += ce; pl1_acc += l1; np_acc += 1; }
    }

    // block stats reduction (once per block)
    #pragma unroll
    for (int o = 16; o > 0; o >>= 1) {
        pce_acc += __shfl_down_sync(0xFFFFFFFFu, pce_acc, o);
        pl1_acc += __shfl_down_sync(0xFFFFFFFFu, pl1_acc, o);
        np_acc  += __shfl_down_sync(0xFFFFFFFFu, np_acc,  o);
    }
    if (lane == 0) {
        atomicAdd(&s_pce, pce_acc);
        atomicAdd(&s_pl1, pl1_acc);
        atomicAdd(&s_np,  np_acc);
    }
    __syncthreads();

    {   // flush 256-bucket hist: one op per thread
        unsigned int c = s_h[tid];
        if (c) atomicAdd(&g_h1[tid], c);
    }
    if (tid == 0) {
        atomicAdd(&g_state.pos_ce_sum, (double)s_pce);
        atomicAdd(&g_state.loc_sum,    (double)s_pl1);
        atomicAdd(&g_state.num_pos,    (unsigned long long)s_np);
        __threadfence();
        unsigned int prev = atomicAdd(&g_ctr[0], 1u);
        s_last = (prev == (unsigned int)gridDim.x - 1u);
    }
    __syncthreads();
    if (!s_last) return;

    // ---- last block: compute k, select 8-bit prefix p1 ----
    if (tid == 0) {
        unsigned long long npos = g_state.num_pos;
        unsigned long long nneg = (unsigned long long)NN - npos;
        unsigned long long k = 3ull * npos;
        if (k > nneg) k = nneg;
        g_state.k = k;
        s_k = k;
    }
    __syncthreads();
    if (s_k == 0ull) {
        if (tid == 0) { g_state.p1 = 0xFFFFFFFFu; g_state.k_rem = 0ull; g_state.cnt_above = 0ull; }
        return;
    }
    unsigned int b; unsigned long long above;
    radix_select<1>(g_h1, s_k, b, above);
    if (tid == 0) {
        g_state.p1 = b;
        g_state.cnt_above = above;
        g_state.k_rem = s_k - above;   // >= 1
    }
}

// ---------------------------------------------------------------------------
// 2. refine1: bits[23:12] hist within 8-bit prefix; extends prefix to 20 bits
// ---------------------------------------------------------------------------
__global__ __launch_bounds__(256) void refine1_kernel() {
    __shared__ unsigned int s_h[4096];
    __shared__ int s_last;
    const int tid = threadIdx.x;
    for (int j = tid; j < 4096; j += 256) s_h[j] = 0u;
    __syncthreads();

    const unsigned int p1 = g_state.p1;     // sentinel matches nothing
    const int stride = gridDim.x * blockDim.x;
    for (int i = blockIdx.x * blockDim.x + tid; i < N4; i += stride) {
        uint4 v = reinterpret_cast<const uint4*>(g_ce_bits)[i];
        if ((v.x >> 24) == p1) atomicAdd(&s_h[(v.x >> 12) & 0xFFFu], 1u);
        if ((v.y >> 24) == p1) atomicAdd(&s_h[(v.y >> 12) & 0xFFFu], 1u);
        if ((v.z >> 24) == p1) atomicAdd(&s_h[(v.z >> 12) & 0xFFFu], 1u);
        if ((v.w >> 24) == p1) atomicAdd(&s_h[(v.w >> 12) & 0xFFFu], 1u);
    }
    __syncthreads();
    for (int j = tid; j < 4096; j += 256) {
        unsigned int c = s_h[j];
        if (c) atomicAdd(&g_h2[j], c);
    }
    if (tid == 0) {
        __threadfence();
        unsigned int prev = atomicAdd(&g_ctr[1], 1u);
        s_last = (prev == (unsigned int)gridDim.x - 1u);
    }
    __syncthreads();
    if (!s_last) return;

    unsigned long long kr = g_state.k_rem;
    if (kr == 0ull) return;                  // k==0: sentinel prefix stays
    unsigned int b; unsigned long long above;
    radix_select<16>(g_h2, kr, b, above);
    if (tid == 0) {
        g_state.p1 = (g_state.p1 << 12) | b; // 20-bit prefix
        g_state.cnt_above += above;
        g_state.k_rem = kr - above;
    }
}

// ---------------------------------------------------------------------------
// 3. final: L3 counts within 20-bit prefix + sum of strictly-above-prefix
//    values; last block selects bucket, reconstructs tail analytically
//    (all elements in one L3 bucket share an identical 32-bit pattern:
//    bucket sum = count * value), finalizes, re-zeros.
// ---------------------------------------------------------------------------
__global__ __launch_bounds__(256) void final_kernel(float* __restrict__ out) {
    __shared__ unsigned int s_h[4096];   // 16 KB
    __shared__ double sh[8];
    __shared__ int s_last;
    const int tid = threadIdx.x;
    for (int j = tid; j < 4096; j += 256) s_h[j] = 0u;
    __syncthreads();

    const unsigned int p20 = g_state.p1;    // 20-bit prefix (or sentinel)
    const int stride = gridDim.x * blockDim.x;
    double gt = 0.0;                        // values with (v>>12) > p20
    for (int i = blockIdx.x * blockDim.x + tid; i < N4; i += stride) {
        uint4 v = reinterpret_cast<const uint4*>(g_ce_bits)[i];
        unsigned int hx = v.x >> 12, hy = v.y >> 12, hz = v.z >> 12, hw = v.w >> 12;
        if (hx > p20) gt += (double)__uint_as_float(v.x);
        else if (hx == p20) atomicAdd(&s_h[v.x & 0xFFFu], 1u);
        if (hy > p20) gt += (double)__uint_as_float(v.y);
        else if (hy == p20) atomicAdd(&s_h[v.y & 0xFFFu], 1u);
        if (hz > p20) gt += (double)__uint_as_float(v.z);
        else if (hz == p20) atomicAdd(&s_h[v.z & 0xFFFu], 1u);
        if (hw > p20) gt += (double)__uint_as_float(v.w);
        else if (hw == p20) atomicAdd(&s_h[v.w & 0xFFFu], 1u);
    }
    #pragma unroll
    for (int o = 16; o > 0; o >>= 1)
        gt += __shfl_down_sync(0xFFFFFFFFu, gt, o);
    const int wid = tid >> 5, lid = tid & 31;
    if (lid == 0) sh[wid] = gt;
    __syncthreads();
    for (int j = tid; j < 4096; j += 256) {
        unsigned int c = s_h[j];
        if (c) atomicAdd(&g_h3[j], c);
    }
    if (tid == 0) {
        double b = 0.0;
        #pragma unroll
        for (int w = 0; w < 8; w++) b += sh[w];
        atomicAdd(&g_state.sum_gt_pre, b);
        __threadfence();
        unsigned int prev = atomicAdd(&g_ctr[2], 1u);
        s_last = (prev == (unsigned int)gridDim.x - 1u);
    }
    __syncthreads();
    if (!s_last) goto done;

    {
        const unsigned long long kr = g_state.k_rem;
        const double np = (double)g_state.num_pos;
        const double kk = (double)g_state.k;

        if (kr == 0ull) {     // k == 0 overall: topk contributes nothing
            if (tid == 0) {
                out[0] = (float)(g_state.pos_ce_sum / (np + kk));
                out[1] = (float)(g_state.loc_sum / np);
            }
        } else {
            unsigned int b; unsigned long long above;
            radix_select<16>(g_h3, kr, b, above);
            // analytic tail: buckets j > b each hold identical values
            double tail = 0.0;
            #pragma unroll
            for (int j = 0; j < 16; j++) {
                int idx = tid * 16 + j;
                if (idx > (int)b) {
                    unsigned int c = g_h3[idx];
                    if (c) tail += (double)c *
                        (double)__uint_as_float((p20 << 12) | (unsigned int)idx);
                }
            }
            #pragma unroll
            for (int o = 16; o > 0; o >>= 1)
                tail += __shfl_down_sync(0xFFFFFFFFu, tail, o);
            if (lid == 0) sh[wid] = tail;
            __syncthreads();
            if (tid == 0) {
                double t2 = 0.0;
                #pragma unroll
                for (int w = 0; w < 8; w++) t2 += sh[w];
                const unsigned int thresh = (p20 << 12) | b;
                const unsigned long long cnt_gt = g_state.cnt_above + above;
                const unsigned long long ties = g_state.k - cnt_gt;
                const double tval = (double)__uint_as_float(thresh);
                const double topk = g_state.sum_gt_pre + t2 + (double)ties * tval;
                out[0] = (float)((g_state.pos_ce_sum + topk) / (np + kk));
                out[1] = (float)(g_state.loc_sum / np);
            }
        }
    }
    __syncthreads();
    // re-zero scratch for the next graph replay
    for (int j = tid; j < 4096; j += 256) { g_h2[j] = 0u; g_h3[j] = 0u; }
    if (tid < 256) g_h1[tid] = 0u;
    if (tid < 3)   g_ctr[tid] = 0u;
    if (tid == 0) {
        g_state.pos_ce_sum = 0.0; g_state.loc_sum = 0.0; g_state.sum_gt_pre = 0.0;
        g_state.num_pos = 0ull; g_state.k = 0ull; g_state.k_rem = 0ull;
        g_state.cnt_above = 0ull;
        g_state.p1 = 0xFFFFFFFFu;
    }
done: ;
}

// ---------------------------------------------------------------------------
// launch: 3 kernels total
// ---------------------------------------------------------------------------
extern "C" void kernel_launch(void* const* d_in, const int* in_sizes, int n_in,
                              void* d_out, int out_size)
{
    const float* pred_loc   = (const float*)d_in[0];
    const float* pred_clf   = (const float*)d_in[1];
    const float* target_loc = (const float*)d_in[2];
    const int*   target_cls = (const int*)  d_in[3];
    float* out = (float*)d_out;

    main_kernel<<<NBLK_MAIN, 256>>>(pred_loc, pred_clf, target_loc, target_cls);
    refine1_kernel<<<PASS_GRID, 256>>>();
    final_kernel<<<PASS_GRID, 256>>>(out);
}

// round 8
// speedup vs baseline: 6.5374x; 1.1735x over previous
#include <cuda_runtime.h>
#include <cstdint>

// Problem constants
#define BB 128
#define AA 8732
#define NN (BB * AA)          // 1,117,696 = 256 * 4366
#define CC 21
#define NTILES (NN / 256)     // 4366
#define TILES_PER_BLK 2
#define NBLK_MAIN (NTILES / TILES_PER_BLK)  // 2183
#define N4 (NN / 4)
#define BACKGROUND 0
#define PASS_GRID 296

// ---------------------------------------------------------------------------
// Device scratch (static zero-init; re-zeroed at the end of every run)
// Radix levels: L1 = bits[31:24] (256), L2 = bits[23:12] (4096), L3 = bits[11:0] (4096)
// ---------------------------------------------------------------------------
__device__ unsigned int g_ce_bits[NN];
__device__ unsigned int g_h1[256];
__device__ unsigned int g_h2[4096];
__device__ unsigned int g_h3[4096];
__device__ unsigned int g_ctr[3];     // last-block tickets: main, r1, final

struct State {
    double pos_ce_sum, loc_sum, sum_gt_pre;  // sum over (v>>12) > p20
    unsigned long long num_pos, k, k_rem, cnt_above;
    unsigned int p1;                          // evolving prefix (8 -> 20 bits)
};
__device__ State g_state;             // zero-init

// ---------------------------------------------------------------------------
// Parallel descending radix-select over a histogram (block-wide broadcast).
// Precondition: 1 <= k <= total count in hist.
// ---------------------------------------------------------------------------
template<int BPT>
__device__ void radix_select(const unsigned int* __restrict__ hist,
                             unsigned long long k,
                             unsigned int& b_out, unsigned long long& above_out)
{
    __shared__ unsigned int ssum[256];
    __shared__ unsigned int s_b;
    __shared__ unsigned long long s_above;
    const int t = threadIdx.x;

    unsigned int cnt[BPT];
    unsigned int tsum = 0;
    #pragma unroll
    for (int j = 0; j < BPT; j++) { cnt[j] = hist[t * BPT + j]; tsum += cnt[j]; }
    ssum[t] = tsum;
    __syncthreads();
    for (int o = 1; o < 256; o <<= 1) {   // inclusive suffix scan (descending)
        unsigned int v = ssum[t] + ((t + o < 256) ? ssum[t + o] : 0u);
        __syncthreads();
        ssum[t] = v;
        __syncthreads();
    }
    unsigned long long incl  = ssum[t];
    unsigned long long above = (t < 255) ? (unsigned long long)ssum[t + 1] : 0ull;
    if (above < k && incl >= k) {         // exactly one owner thread
        unsigned long long a = above;
        int b = t * BPT;
        #pragma unroll
        for (int j = BPT - 1; j >= 0; j--) {
            unsigned long long c = cnt[j];
            if (a + c >= k) { b = t * BPT + j; break; }
            a += c;
        }
        s_b = (unsigned int)b;
        s_above = a;
    }
    __syncthreads();
    b_out = s_b;
    above_out = s_above;
}

// ---------------------------------------------------------------------------
// 1. main fused pass: 2 tiles/block, cp.async staging overlapped with the
//    independent loc/cls loads. CE, loc-L1, ce_bits, warp-aggregated 256-bucket
//    L1 hist; last block computes k and selects p1.
// ---------------------------------------------------------------------------
__global__ __launch_bounds__(256) void main_kernel(
    const float* __restrict__ pred_loc,
    const float* __restrict__ pred_clf,
    const float* __restrict__ target_loc,
    const int*   __restrict__ target_cls)
{
    __shared__ float s_clf[256 * CC];        // 21504 B
    __shared__ unsigned int s_h[256];        // 1024 B
    __shared__ float s_pce, s_pl1;
    __shared__ int   s_np;
    __shared__ int   s_last;
    __shared__ unsigned long long s_k;

    const int tid = threadIdx.x;
    const int lane = tid & 31;

    if (tid == 0) { s_pce = 0.f; s_pl1 = 0.f; s_np = 0; }
    s_h[tid] = 0u;

    float pce_acc = 0.f, pl1_acc = 0.f;
    int np_acc = 0;

    const unsigned int smem_clf =
        (unsigned int)__cvta_generic_to_shared(s_clf);

    const int tile0 = blockIdx.x * TILES_PER_BLK;
    #pragma unroll
    for (int t = 0; t < TILES_PER_BLK; t++) {
        const int a0 = (tile0 + t) * 256;

        __syncthreads();     // s_clf reuse: previous tile's readers done

        // async stage 256*21 floats (1344 x 16B) global -> shared
        {
            const char* src = reinterpret_cast<const char*>(pred_clf) + (size_t)a0 * CC * 4;
            #pragma unroll
            for (int j = tid; j < (256 * CC) / 4; j += 256) {
                asm volatile("cp.async.cg.shared.global [%0], [%1], 16;\n"
                             :: "r"(smem_clf + j * 16), "l"(src + (size_t)j * 16));
            }
            asm volatile("cp.async.commit_group;\n");
        }

        // independent loads overlap with the bulk copy
        const int a    = a0 + tid;
        const int tcls = target_cls[a];
        const float4 pl = reinterpret_cast<const float4*>(pred_loc)[a];
        const float4 tl = reinterpret_cast<const float4*>(target_loc)[a];

        asm volatile("cp.async.wait_group 0;\n");
        __syncthreads();

        const bool pos = (tcls != BACKGROUND);

        // log-softmax CE (stride-21 shared reads: gcd(21,32)=1 -> conflict-free)
        const float* x = s_clf + tid * CC;
        float mx = x[0];
        #pragma unroll
        for (int c = 1; c < CC; c++) mx = fmaxf(mx, x[c]);
        float se = 0.f;
        #pragma unroll
        for (int c = 0; c < CC; c++) se += __expf(x[c] - mx);
        float ce = mx + __logf(se) - x[tcls];
        ce = fmaxf(ce, 0.f);

        // negatives carry CE bits; positives carry 0 (adds 0 to any top-k sum)
        const unsigned int bits = pos ? 0u : __float_as_uint(ce);
        g_ce_bits[a] = bits;

        // warp-aggregated 256-bucket histogram update (CE clusters -> hot bucket)
        {
            const unsigned int bkt = bits >> 24;
            unsigned int mask = __match_any_sync(0xFFFFFFFFu, bkt);
            if ((int)(__ffs(mask) - 1) == lane)
                atomicAdd(&s_h[bkt], (unsigned int)__popc(mask));
        }

        const float l1 = fabsf(pl.x - tl.x) + fabsf(pl.y - tl.y)
                       + fabsf(pl.z - tl.z) + fabsf(pl.w - tl.w);
        if (pos) { pce_acc += ce; pl1_acc += l1; np_acc += 1; }
    }

    // block stats reduction (once per block)
    #pragma unroll
    for (int o = 16; o > 0; o >>= 1) {
        pce_acc += __shfl_down_sync(0xFFFFFFFFu, pce_acc, o);
        pl1_acc += __shfl_down_sync(0xFFFFFFFFu, pl1_acc, o);
        np_acc  += __shfl_down_sync(0xFFFFFFFFu, np_acc,  o);
    }
    if (lane == 0) {
        atomicAdd(&s_pce, pce_acc);
        atomicAdd(&s_pl1, pl1_acc);
        atomicAdd(&s_np,  np_acc);
    }
    __syncthreads();

    {   // flush 256-bucket hist: one op per thread
        unsigned int c = s_h[tid];
        if (c) atomicAdd(&g_h1[tid], c);
    }
    if (tid == 0) {
        atomicAdd(&g_state.pos_ce_sum, (double)s_pce);
        atomicAdd(&g_state.loc_sum,    (double)s_pl1);
        atomicAdd(&g_state.num_pos,    (unsigned long long)s_np);
        __threadfence();
        unsigned int prev = atomicAdd(&g_ctr[0], 1u);
        s_last = (prev == (unsigned int)gridDim.x - 1u);
    }
    __syncthreads();
    if (!s_last) return;

    // ---- last block: compute k, select 8-bit prefix p1 ----
    if (tid == 0) {
        unsigned long long npos = g_state.num_pos;
        unsigned long long nneg = (unsigned long long)NN - npos;
        unsigned long long k = 3ull * npos;
        if (k > nneg) k = nneg;
        g_state.k = k;
        s_k = k;
    }
    __syncthreads();
    if (s_k == 0ull) {
        if (tid == 0) { g_state.p1 = 0xFFFFFFFFu; g_state.k_rem = 0ull; g_state.cnt_above = 0ull; }
        return;
    }
    unsigned int b; unsigned long long above;
    radix_select<1>(g_h1, s_k, b, above);
    if (tid == 0) {
        g_state.p1 = b;
        g_state.cnt_above = above;
        g_state.k_rem = s_k - above;   // >= 1
    }
}

// ---------------------------------------------------------------------------
// 2. refine1: bits[23:12] hist within 8-bit prefix; extends prefix to 20 bits
// ---------------------------------------------------------------------------
__global__ __launch_bounds__(256) void refine1_kernel() {
    __shared__ unsigned int s_h[4096];
    __shared__ int s_last;
    const int tid = threadIdx.x;
    for (int j = tid; j < 4096; j += 256) s_h[j] = 0u;
    __syncthreads();

    const unsigned int p1 = g_state.p1;     // sentinel matches nothing
    const int stride = gridDim.x * blockDim.x;
    for (int i = blockIdx.x * blockDim.x + tid; i < N4; i += stride) {
        uint4 v = reinterpret_cast<const uint4*>(g_ce_bits)[i];
        if ((v.x >> 24) == p1) atomicAdd(&s_h[(v.x >> 12) & 0xFFFu], 1u);
        if ((v.y >> 24) == p1) atomicAdd(&s_h[(v.y >> 12) & 0xFFFu], 1u);
        if ((v.z >> 24) == p1) atomicAdd(&s_h[(v.z >> 12) & 0xFFFu], 1u);
        if ((v.w >> 24) == p1) atomicAdd(&s_h[(v.w >> 12) & 0xFFFu], 1u);
    }
    __syncthreads();
    for (int j = tid; j < 4096; j += 256) {
        unsigned int c = s_h[j];
        if (c) atomicAdd(&g_h2[j], c);
    }
    if (tid == 0) {
        __threadfence();
        unsigned int prev = atomicAdd(&g_ctr[1], 1u);
        s_last = (prev == (unsigned int)gridDim.x - 1u);
    }
    __syncthreads();
    if (!s_last) return;

    unsigned long long kr = g_state.k_rem;
    if (kr == 0ull) return;                  // k==0: sentinel prefix stays
    unsigned int b; unsigned long long above;
    radix_select<16>(g_h2, kr, b, above);
    if (tid == 0) {
        g_state.p1 = (g_state.p1 << 12) | b; // 20-bit prefix
        g_state.cnt_above += above;
        g_state.k_rem = kr - above;
    }
}

// ---------------------------------------------------------------------------
// 3. final: L3 counts within 20-bit prefix + sum of strictly-above-prefix
//    values; last block selects bucket, reconstructs tail analytically
//    (all elements in one L3 bucket share an identical 32-bit pattern:
//    bucket sum = count * value), finalizes, re-zeros.
// ---------------------------------------------------------------------------
__global__ __launch_bounds__(256) void final_kernel(float* __restrict__ out) {
    __shared__ unsigned int s_h[4096];   // 16 KB
    __shared__ double sh[8];
    __shared__ int s_last;
    const int tid = threadIdx.x;
    for (int j = tid; j < 4096; j += 256) s_h[j] = 0u;
    __syncthreads();

    const unsigned int p20 = g_state.p1;    // 20-bit prefix (or sentinel)
    const int stride = gridDim.x * blockDim.x;
    double gt = 0.0;                        // values with (v>>12) > p20
    for (int i = blockIdx.x * blockDim.x + tid; i < N4; i += stride) {
        uint4 v = reinterpret_cast<const uint4*>(g_ce_bits)[i];
        unsigned int hx = v.x >> 12, hy = v.y >> 12, hz = v.z >> 12, hw = v.w >> 12;
        if (hx > p20) gt += (double)__uint_as_float(v.x);
        else if (hx == p20) atomicAdd(&s_h[v.x & 0xFFFu], 1u);
        if (hy > p20) gt += (double)__uint_as_float(v.y);
        else if (hy == p20) atomicAdd(&s_h[v.y & 0xFFFu], 1u);
        if (hz > p20) gt += (double)__uint_as_float(v.z);
        else if (hz == p20) atomicAdd(&s_h[v.z & 0xFFFu], 1u);
        if (hw > p20) gt += (double)__uint_as_float(v.w);
        else if (hw == p20) atomicAdd(&s_h[v.w & 0xFFFu], 1u);
    }
    #pragma unroll
    for (int o = 16; o > 0; o >>= 1)
        gt += __shfl_down_sync(0xFFFFFFFFu, gt, o);
    const int wid = tid >> 5, lid = tid & 31;
    if (lid == 0) sh[wid] = gt;
    __syncthreads();
    for (int j = tid; j < 4096; j += 256) {
        unsigned int c = s_h[j];
        if (c) atomicAdd(&g_h3[j], c);
    }
    if (tid == 0) {
        double b = 0.0;
        #pragma unroll
        for (int w = 0; w < 8; w++) b += sh[w];
        atomicAdd(&g_state.sum_gt_pre, b);
        __threadfence();
        unsigned int prev = atomicAdd(&g_ctr[2], 1u);
        s_last = (prev == (unsigned int)gridDim.x - 1u);
    }
    __syncthreads();
    if (!s_last) goto done;

    {
        const unsigned long long kr = g_state.k_rem;
        const double np = (double)g_state.num_pos;
        const double kk = (double)g_state.k;

        if (kr == 0ull) {     // k == 0 overall: topk contributes nothing
            if (tid == 0) {
                out[0] = (float)(g_state.pos_ce_sum / (np + kk));
                out[1] = (float)(g_state.loc_sum / np);
            }
        } else {
            unsigned int b; unsigned long long above;
            radix_select<16>(g_h3, kr, b, above);
            // analytic tail: buckets j > b each hold identical values
            double tail = 0.0;
            #pragma unroll
            for (int j = 0; j < 16; j++) {
                int idx = tid * 16 + j;
                if (idx > (int)b) {
                    unsigned int c = g_h3[idx];
                    if (c) tail += (double)c *
                        (double)__uint_as_float((p20 << 12) | (unsigned int)idx);
                }
            }
            #pragma unroll
            for (int o = 16; o > 0; o >>= 1)
                tail += __shfl_down_sync(0xFFFFFFFFu, tail, o);
            if (lid == 0) sh[wid] = tail;
            __syncthreads();
            if (tid == 0) {
                double t2 = 0.0;
                #pragma unroll
                for (int w = 0; w < 8; w++) t2 += sh[w];
                const unsigned int thresh = (p20 << 12) | b;
                const unsigned long long cnt_gt = g_state.cnt_above + above;
                const unsigned long long ties = g_state.k - cnt_gt;
                const double tval = (double)__uint_as_float(thresh);
                const double topk = g_state.sum_gt_pre + t2 + (double)ties * tval;
                out[0] = (float)((g_state.pos_ce_sum + topk) / (np + kk));
                out[1] = (float)(g_state.loc_sum / np);
            }
        }
    }
    __syncthreads();
    // re-zero scratch for the next graph replay
    for (int j = tid; j < 4096; j += 256) { g_h2[j] = 0u; g_h3[j] = 0u; }
    if (tid < 256) g_h1[tid] = 0u;
    if (tid < 3)   g_ctr[tid] = 0u;
    if (tid == 0) {
        g_state.pos_ce_sum = 0.0; g_state.loc_sum = 0.0; g_state.sum_gt_pre = 0.0;
        g_state.num_pos = 0ull; g_state.k = 0ull; g_state.k_rem = 0ull;
        g_state.cnt_above = 0ull;
        g_state.p1 = 0xFFFFFFFFu;
    }
done: ;
}

// ---------------------------------------------------------------------------
// launch: 3 kernels total
// ---------------------------------------------------------------------------
extern "C" void kernel_launch(void* const* d_in, const int* in_sizes, int n_in,
                              void* d_out, int out_size)
{
    const float* pred_loc   = (const float*)d_in[0];
    const float* pred_clf   = (const float*)d_in[1];
    const float* target_loc = (const float*)d_in[2];
    const int*   target_cls = (const int*)  d_in[3];
    float* out = (float*)d_out;

    main_kernel<<<NBLK_MAIN, 256>>>(pred_loc, pred_clf, target_loc, target_cls);
    refine1_kernel<<<PASS_GRID, 256>>>();
    final_kernel<<<PASS_GRID, 256>>>(out);
}

// round 10
// speedup vs baseline: 6.5450x; 1.0012x over previous
#include <cuda_runtime.h>
#include <cstdint>

// Problem constants
#define BB 128
#define AA 8732
#define NN (BB * AA)          // 1,117,696 = 256 * 4366
#define CC 21
#define NTILES (NN / 256)     // 4366
#define TILES_PER_BLK 2
#define NBLK_MAIN (NTILES / TILES_PER_BLK)  // 2183
#define N4 (NN / 4)
#define BACKGROUND 0
#define PASS_GRID 296

// ---------------------------------------------------------------------------
// Device scratch (static zero-init; re-zeroed at the end of every run)
// Radix levels: L1 = bits[31:24] (256), L2 = bits[23:12] (4096), L3 = bits[11:0] (4096)
// ---------------------------------------------------------------------------
__device__ unsigned int g_ce_bits[NN];
__device__ unsigned int g_h1[256];
__device__ unsigned int g_h2[4096];
__device__ unsigned int g_h3[4096];
__device__ unsigned int g_ctr[3];     // last-block tickets: main, r1, final

struct State {
    double pos_ce_sum, loc_sum, sum_gt_pre;  // sum over (v>>12) > p20
    unsigned long long num_pos, k, k_rem, cnt_above;
    unsigned int p1;                          // evolving prefix (8 -> 20 bits)
};
__device__ State g_state;             // zero-init

// ---------------------------------------------------------------------------
// Parallel descending radix-select over a histogram (block-wide broadcast).
// Precondition: 1 <= k <= total count in hist. blockDim.x == 256.
// ---------------------------------------------------------------------------
template<int BPT>
__device__ void radix_select(const unsigned int* __restrict__ hist,
                             unsigned long long k,
                             unsigned int& b_out, unsigned long long& above_out)
{
    __shared__ unsigned int ssum[256];
    __shared__ unsigned int s_b;
    __shared__ unsigned long long s_above;
    const int t = threadIdx.x;

    unsigned int cnt[BPT];
    unsigned int tsum = 0;
    #pragma unroll
    for (int j = 0; j < BPT; j++) { cnt[j] = hist[t * BPT + j]; tsum += cnt[j]; }
    ssum[t] = tsum;
    __syncthreads();
    for (int o = 1; o < 256; o <<= 1) {   // inclusive suffix scan (descending)
        unsigned int v = ssum[t] + ((t + o < 256) ? ssum[t + o] : 0u);
        __syncthreads();
        ssum[t] = v;
        __syncthreads();
    }
    unsigned long long incl  = ssum[t];
    unsigned long long above = (t < 255) ? (unsigned long long)ssum[t + 1] : 0ull;
    if (above < k && incl >= k) {         // exactly one owner thread
        unsigned long long a = above;
        int b = t * BPT;
        #pragma unroll
        for (int j = BPT - 1; j >= 0; j--) {
            unsigned long long c = cnt[j];
            if (a + c >= k) { b = t * BPT + j; break; }
            a += c;
        }
        s_b = (unsigned int)b;
        s_above = a;
    }
    __syncthreads();
    b_out = s_b;
    above_out = s_above;
}

// ---------------------------------------------------------------------------
// 1. main fused pass: 2 tiles/block, cp.async staging overlapped with the
//    independent loc/cls loads. Forced to 32 regs for 8 CTAs/SM.
// ---------------------------------------------------------------------------
__global__ __launch_bounds__(256, 8) void main_kernel(
    const float* __restrict__ pred_loc,
    const float* __restrict__ pred_clf,
    const float* __restrict__ target_loc,
    const int*   __restrict__ target_cls)
{
    __shared__ float s_clf[256 * CC];        // 21504 B
    __shared__ unsigned int s_h[256];        // 1024 B
    __shared__ float s_pce, s_pl1;
    __shared__ int   s_np;
    __shared__ int   s_last;
    __shared__ unsigned long long s_k;

    const int tid = threadIdx.x;
    const int lane = tid & 31;

    if (tid == 0) { s_pce = 0.f; s_pl1 = 0.f; s_np = 0; }
    s_h[tid] = 0u;

    float pce_acc = 0.f, pl1_acc = 0.f;
    int np_acc = 0;

    const unsigned int smem_clf =
        (unsigned int)__cvta_generic_to_shared(s_clf);

    const int tile0 = blockIdx.x * TILES_PER_BLK;
    #pragma unroll
    for (int t = 0; t < TILES_PER_BLK; t++) {
        const int a0 = (tile0 + t) * 256;

        __syncthreads();     // s_clf reuse: previous tile's readers done

        // async stage 256*21 floats (1344 x 16B) global -> shared
        {
            const char* src = reinterpret_cast<const char*>(pred_clf) + (size_t)a0 * CC * 4;
            #pragma unroll
            for (int j = tid; j < (256 * CC) / 4; j += 256) {
                asm volatile("cp.async.cg.shared.global [%0], [%1], 16;\n"
                             :: "r"(smem_clf + j * 16), "l"(src + (size_t)j * 16));
            }
            asm volatile("cp.async.commit_group;\n");
        }

        // independent loads overlap with the bulk copy; consume loc values
        // immediately so their 8 registers die before the CE section
        const int a    = a0 + tid;
        const int tc   = target_cls[a];
        const bool pos = (tc != BACKGROUND);
        const int tcls = pos ? tc : 0;
        float l1;
        {
            const float4 pl = reinterpret_cast<const float4*>(pred_loc)[a];
            const float4 tl = reinterpret_cast<const float4*>(target_loc)[a];
            l1 = fabsf(pl.x - tl.x) + fabsf(pl.y - tl.y)
               + fabsf(pl.z - tl.z) + fabsf(pl.w - tl.w);
        }

        asm volatile("cp.async.wait_group 0;\n");
        __syncthreads();

        // log-softmax CE (stride-21 shared reads: gcd(21,32)=1 -> conflict-free)
        const float* x = s_clf + tid * CC;
        float mx = x[0];
        #pragma unroll
        for (int c = 1; c < CC; c++) mx = fmaxf(mx, x[c]);
        float se = 0.f;
        #pragma unroll
        for (int c = 0; c < CC; c++) se += __expf(x[c] - mx);
        float ce = mx + __logf(se) - x[tcls];
        ce = fmaxf(ce, 0.f);

        // negatives carry CE bits; positives carry 0 (adds 0 to any top-k sum)
        const unsigned int bits = pos ? 0u : __float_as_uint(ce);
        g_ce_bits[a] = bits;

        // warp-aggregated 256-bucket histogram update (CE clusters -> hot bucket)
        {
            const unsigned int bkt = bits >> 24;
            unsigned int mask = __match_any_sync(0xFFFFFFFFu, bkt);
            if ((int)(__ffs(mask) - 1) == lane)
                atomicAdd(&s_h[bkt], (unsigned int)__popc(mask));
        }

        if (pos) { pce_acc += ce; pl1_acc += l1; np_acc += 1; }
    }

    // block stats reduction (once per block)
    #pragma unroll
    for (int o = 16; o > 0; o >>= 1) {
        pce_acc += __shfl_down_sync(0xFFFFFFFFu, pce_acc, o);
        pl1_acc += __shfl_down_sync(0xFFFFFFFFu, pl1_acc, o);
        np_acc  += __shfl_down_sync(0xFFFFFFFFu, np_acc,  o);
    }
    if (lane == 0) {
        atomicAdd(&s_pce, pce_acc);
        atomicAdd(&s_pl1, pl1_acc);
        atomicAdd(&s_np,  np_acc);
    }
    __syncthreads();

    {   // flush 256-bucket hist: one op per thread
        unsigned int c = s_h[tid];
        if (c) atomicAdd(&g_h1[tid], c);
    }
    if (tid == 0) {
        atomicAdd(&g_state.pos_ce_sum, (double)s_pce);
        atomicAdd(&g_state.loc_sum,    (double)s_pl1);
        atomicAdd(&g_state.num_pos,    (unsigned long long)s_np);
        __threadfence();
        unsigned int prev = atomicAdd(&g_ctr[0], 1u);
        s_last = (prev == (unsigned int)gridDim.x - 1u);
    }
    __syncthreads();
    if (!s_last) return;

    // ---- last block: compute k, select 8-bit prefix p1 ----
    if (tid == 0) {
        unsigned long long npos = g_state.num_pos;
        unsigned long long nneg = (unsigned long long)NN - npos;
        unsigned long long k = 3ull * npos;
        if (k > nneg) k = nneg;
        g_state.k = k;
        s_k = k;
    }
    __syncthreads();
    if (s_k == 0ull) {
        if (tid == 0) { g_state.p1 = 0xFFFFFFFFu; g_state.k_rem = 0ull; g_state.cnt_above = 0ull; }
        return;
    }
    unsigned int b; unsigned long long above;
    radix_select<1>(g_h1, s_k, b, above);
    if (tid == 0) {
        g_state.p1 = b;
        g_state.cnt_above = above;
        g_state.k_rem = s_k - above;   // >= 1
    }
}

// ---------------------------------------------------------------------------
// 2. refine1: bits[23:12] hist within 8-bit prefix; extends prefix to 20 bits
// ---------------------------------------------------------------------------
__global__ __launch_bounds__(256) void refine1_kernel() {
    __shared__ unsigned int s_h[4096];
    __shared__ int s_last;
    const int tid = threadIdx.x;
    for (int j = tid; j < 4096; j += 256) s_h[j] = 0u;
    __syncthreads();

    const unsigned int p1 = g_state.p1;     // sentinel matches nothing
    const int stride = gridDim.x * blockDim.x;
    for (int i = blockIdx.x * blockDim.x + tid; i < N4; i += stride) {
        uint4 v = reinterpret_cast<const uint4*>(g_ce_bits)[i];
        if ((v.x >> 24) == p1) atomicAdd(&s_h[(v.x >> 12) & 0xFFFu], 1u);
        if ((v.y >> 24) == p1) atomicAdd(&s_h[(v.y >> 12) & 0xFFFu], 1u);
        if ((v.z >> 24) == p1) atomicAdd(&s_h[(v.z >> 12) & 0xFFFu], 1u);
        if ((v.w >> 24) == p1) atomicAdd(&s_h[(v.w >> 12) & 0xFFFu], 1u);
    }
    __syncthreads();
    for (int j = tid; j < 4096; j += 256) {
        unsigned int c = s_h[j];
        if (c) atomicAdd(&g_h2[j], c);
    }
    if (tid == 0) {
        __threadfence();
        unsigned int prev = atomicAdd(&g_ctr[1], 1u);
        s_last = (prev == (unsigned int)gridDim.x - 1u);
    }
    __syncthreads();
    if (!s_last) return;

    unsigned long long kr = g_state.k_rem;
    if (kr == 0ull) return;                  // k==0: sentinel prefix stays
    unsigned int b; unsigned long long above;
    radix_select<16>(g_h2, kr, b, above);
    if (tid == 0) {
        g_state.p1 = (g_state.p1 << 12) | b; // 20-bit prefix
        g_state.cnt_above += above;
        g_state.k_rem = kr - above;
    }
}

// ---------------------------------------------------------------------------
// 3. final: L3 counts within 20-bit prefix + sum of strictly-above-prefix
//    values; last block selects bucket, reconstructs tail analytically
//    (all elements in one L3 bucket share an identical 32-bit pattern:
//    bucket sum = count * value), finalizes, re-zeros.
// ---------------------------------------------------------------------------
__global__ __launch_bounds__(256) void final_kernel(float* __restrict__ out) {
    __shared__ unsigned int s_h[4096];   // 16 KB
    __shared__ double sh[8];
    __shared__ int s_last;
    const int tid = threadIdx.x;
    for (int j = tid; j < 4096; j += 256) s_h[j] = 0u;
    __syncthreads();

    const unsigned int p20 = g_state.p1;    // 20-bit prefix (or sentinel)
    const int stride = gridDim.x * blockDim.x;
    double gt = 0.0;                        // values with (v>>12) > p20
    for (int i = blockIdx.x * blockDim.x + tid; i < N4; i += stride) {
        uint4 v = reinterpret_cast<const uint4*>(g_ce_bits)[i];
        unsigned int hx = v.x >> 12, hy = v.y >> 12, hz = v.z >> 12, hw = v.w >> 12;
        if (hx > p20) gt += (double)__uint_as_float(v.x);
        else if (hx == p20) atomicAdd(&s_h[v.x & 0xFFFu], 1u);
        if (hy > p20) gt += (double)__uint_as_float(v.y);
        else if (hy == p20) atomicAdd(&s_h[v.y & 0xFFFu], 1u);
        if (hz > p20) gt += (double)__uint_as_float(v.z);
        else if (hz == p20) atomicAdd(&s_h[v.z & 0xFFFu], 1u);
        if (hw > p20) gt += (double)__uint_as_float(v.w);
        else if (hw == p20) atomicAdd(&s_h[v.w & 0xFFFu], 1u);
    }
    #pragma unroll
    for (int o = 16; o > 0; o >>= 1)
        gt += __shfl_down_sync(0xFFFFFFFFu, gt, o);
    const int wid = tid >> 5, lid = tid & 31;
    if (lid == 0) sh[wid] = gt;
    __syncthreads();
    for (int j = tid; j < 4096; j += 256) {
        unsigned int c = s_h[j];
        if (c) atomicAdd(&g_h3[j], c);
    }
    if (tid == 0) {
        double b = 0.0;
        #pragma unroll
        for (int w = 0; w < 8; w++) b += sh[w];
        atomicAdd(&g_state.sum_gt_pre, b);
        __threadfence();
        unsigned int prev = atomicAdd(&g_ctr[2], 1u);
        s_last = (prev == (unsigned int)gridDim.x - 1u);
    }
    __syncthreads();
    if (!s_last) goto done;

    {
        const unsigned long long kr = g_state.k_rem;
        const double np = (double)g_state.num_pos;
        const double kk = (double)g_state.k;

        if (kr == 0ull) {     // k == 0 overall: topk contributes nothing
            if (tid == 0) {
                out[0] = (float)(g_state.pos_ce_sum / (np + kk));
                out[1] = (float)(g_state.loc_sum / np);
            }
        } else {
            unsigned int b; unsigned long long above;
            radix_select<16>(g_h3, kr, b, above);
            // analytic tail: buckets j > b each hold identical values
            double tail = 0.0;
            #pragma unroll
            for (int j = 0; j < 16; j++) {
                int idx = tid * 16 + j;
                if (idx > (int)b) {
                    unsigned int c = g_h3[idx];
                    if (c) tail += (double)c *
                        (double)__uint_as_float((p20 << 12) | (unsigned int)idx);
                }
            }
            #pragma unroll
            for (int o = 16; o > 0; o >>= 1)
                tail += __shfl_down_sync(0xFFFFFFFFu, tail, o);
            if (lid == 0) sh[wid] = tail;
            __syncthreads();
            if (tid == 0) {
                double t2 = 0.0;
                #pragma unroll
                for (int w = 0; w < 8; w++) t2 += sh[w];
                const unsigned int thresh = (p20 << 12) | b;
                const unsigned long long cnt_gt = g_state.cnt_above + above;
                const unsigned long long ties = g_state.k - cnt_gt;
                const double tval = (double)__uint_as_float(thresh);
                const double topk = g_state.sum_gt_pre + t2 + (double)ties * tval;
                out[0] = (float)((g_state.pos_ce_sum + topk) / (np + kk));
                out[1] = (float)(g_state.loc_sum / np);
            }
        }
    }
    __syncthreads();
    // re-zero scratch for the next graph replay
    for (int j = tid; j < 4096; j += 256) { g_h2[j] = 0u; g_h3[j] = 0u; }
    if (tid < 256) g_h1[tid] = 0u;
    if (tid < 3)   g_ctr[tid] = 0u;
    if (tid == 0) {
        g_state.pos_ce_sum = 0.0; g_state.loc_sum = 0.0; g_state.sum_gt_pre = 0.0;
        g_state.num_pos = 0ull; g_state.k = 0ull; g_state.k_rem = 0ull;
        g_state.cnt_above = 0ull;
        g_state.p1 = 0xFFFFFFFFu;
    }
done: ;
}

// ---------------------------------------------------------------------------
// launch: 3 kernels total
// ---------------------------------------------------------------------------
extern "C" void kernel_launch(void* const* d_in, const int* in_sizes, int n_in,
                              void* d_out, int out_size)
{
    const float* pred_loc   = (const float*)d_in[0];
    const float* pred_clf   = (const float*)d_in[1];
    const float* target_loc = (const float*)d_in[2];
    const int*   target_cls = (const int*)  d_in[3];
    float* out = (float*)d_out;

    main_kernel<<<NBLK_MAIN, 256>>>(pred_loc, pred_clf, target_loc, target_cls);
    refine1_kernel<<<PASS_GRID, 256>>>();
    final_kernel<<<PASS_GRID, 256>>>(out);
}